// round 2
// baseline (speedup 1.0000x reference)
#include <cuda_runtime.h>
#include <math.h>

#define MAXN 100000

// ---------------- scratch (device globals; no allocation allowed) ----------
__device__ float g_apsum[MAXN * 64];   // layer1 pos sum
__device__ float g_ansum[MAXN * 64];   // layer1 neg sum
__device__ float g_cntp[MAXN];
__device__ float g_cntn[MAXN];
__device__ float g_zp[MAXN * 32];
__device__ float g_zn[MAXN * 32];
__device__ float g_szpp[MAXN * 32];    // sum of zp over pos edges
__device__ float g_sznp[MAXN * 32];    // sum of zn over pos edges
__device__ float g_sznn[MAXN * 32];    // sum of zn over neg edges
__device__ float g_szpn[MAXN * 32];    // sum of zp over neg edges
__device__ int   g_is64;               // edge-index dtype flag (1 = int64, 0 = int32)

// ---------------- helpers ---------------------------------------------------
__device__ __forceinline__ void red_add_v4(float* addr, float4 v) {
    asm volatile("red.global.add.v4.f32 [%0], {%1, %2, %3, %4};"
                 :: "l"(addr), "f"(v.x), "f"(v.y), "f"(v.z), "f"(v.w)
                 : "memory");
}

__device__ __forceinline__ int load_idx(const void* ei, long long pos, int is64) {
    if (is64) return (int)__ldg((const long long*)ei + pos);
    return __ldg((const int*)ei + pos);
}

// acc[32] += in_k(4 values) * W[kb..kb+3][0..31]  (W in shared, row-major 32 wide)
__device__ __forceinline__ void acc_chunk(float acc[32], const float* Ws, int kb,
                                          float i0, float i1, float i2, float i3) {
    const float4* w0 = (const float4*)(Ws + (kb + 0) * 32);
    const float4* w1 = (const float4*)(Ws + (kb + 1) * 32);
    const float4* w2 = (const float4*)(Ws + (kb + 2) * 32);
    const float4* w3 = (const float4*)(Ws + (kb + 3) * 32);
#pragma unroll
    for (int jj = 0; jj < 8; jj++) {
        float4 a = w0[jj], b = w1[jj], c = w2[jj], d = w3[jj];
        acc[jj * 4 + 0] = fmaf(i0, a.x, fmaf(i1, b.x, fmaf(i2, c.x, fmaf(i3, d.x, acc[jj * 4 + 0]))));
        acc[jj * 4 + 1] = fmaf(i0, a.y, fmaf(i1, b.y, fmaf(i2, c.y, fmaf(i3, d.y, acc[jj * 4 + 1]))));
        acc[jj * 4 + 2] = fmaf(i0, a.z, fmaf(i1, b.z, fmaf(i2, c.z, fmaf(i3, d.z, acc[jj * 4 + 2]))));
        acc[jj * 4 + 3] = fmaf(i0, a.w, fmaf(i1, b.w, fmaf(i2, c.w, fmaf(i3, d.w, acc[jj * 4 + 3]))));
    }
}

// ---------------- dtype detection -------------------------------------------
// If edge buffer is int64 with values < 2^31, every odd 32-bit word of the
// first 256 is zero. For int32 random indices that's astronomically unlikely.
__global__ void detect_dtype(const unsigned int* __restrict__ p) {
    int is64 = 1;
    for (int i = 1; i < 256; i += 2)
        if (p[i] != 0u) { is64 = 0; break; }
    g_is64 = is64;
}

// ---------------- zeroing ----------------------------------------------------
__global__ void zero_all(int n) {
    const float4 z = make_float4(0.f, 0.f, 0.f, 0.f);
    int tid = blockIdx.x * blockDim.x + threadIdx.x;
    int stride = gridDim.x * blockDim.x;
    int n16 = n * 16;  // float4 count for 64-wide arrays
    int n8  = n * 8;   // float4 count for 32-wide arrays
    for (int i = tid; i < n16; i += stride) { ((float4*)g_apsum)[i] = z; ((float4*)g_ansum)[i] = z; }
    for (int i = tid; i < n8;  i += stride) {
        ((float4*)g_szpp)[i] = z; ((float4*)g_sznp)[i] = z;
        ((float4*)g_sznn)[i] = z; ((float4*)g_szpn)[i] = z;
    }
    for (int i = tid; i < n;   i += stride) { g_cntp[i] = 0.f; g_cntn[i] = 0.f; }
}

// ---------------- layer-1 edge scatter (x, 64 feats) + counts ---------------
// sign: 1 -> pos (g_apsum, g_cntp), 0 -> neg (g_ansum, g_cntn)
__global__ void edge_l1(const void* __restrict__ ei, const float* __restrict__ x,
                        int E, int sign) {
    float* __restrict__ sum = sign ? g_apsum : g_ansum;
    float* __restrict__ cnt = sign ? g_cntp : g_cntn;
    const int is64 = g_is64;
    long long total = (long long)E * 16;
    long long stride = (long long)gridDim.x * blockDim.x;
    for (long long item = (long long)blockIdx.x * blockDim.x + threadIdx.x;
         item < total; item += stride) {
        int e = (int)(item >> 4);
        int c = (int)(item & 15);
        int s = load_idx(ei, e, is64);
        int d = load_idx(ei, (long long)E + e, is64);
        float4 v = __ldg((const float4*)x + (size_t)s * 16 + c);
        red_add_v4(sum + (size_t)d * 64 + c * 4, v);
        if (c == 0) atomicAdd(cnt + d, 1.0f);
    }
}

// ---------------- layer-1 node update: zp = tanh([ap,x]W1p+b), zn = ... -----
__global__ void node_l1(const float* __restrict__ x,
                        const float* __restrict__ W1p, const float* __restrict__ b1p,
                        const float* __restrict__ W1n, const float* __restrict__ b1n,
                        int n) {
    __shared__ float Wp[128 * 32];
    __shared__ float Wn[128 * 32];
    for (int t = threadIdx.x; t < 128 * 32; t += blockDim.x) { Wp[t] = W1p[t]; Wn[t] = W1n[t]; }
    __syncthreads();
    int i = blockIdx.x * blockDim.x + threadIdx.x;
    if (i >= n) return;

    float invp = 1.f / fmaxf(g_cntp[i], 1.f);
    float invn = 1.f / fmaxf(g_cntn[i], 1.f);
    const float4* x4 = (const float4*)x + (size_t)i * 16;

    // positive branch
    {
        float acc[32];
#pragma unroll
        for (int j = 0; j < 32; j++) acc[j] = 0.f;
        const float4* a4 = (const float4*)g_apsum + (size_t)i * 16;
#pragma unroll 2
        for (int kk = 0; kk < 16; kk++) {
            float4 v = a4[kk];
            acc_chunk(acc, Wp, kk * 4, v.x * invp, v.y * invp, v.z * invp, v.w * invp);
        }
#pragma unroll 2
        for (int kk = 0; kk < 16; kk++) {
            float4 v = x4[kk];
            acc_chunk(acc, Wp, 64 + kk * 4, v.x, v.y, v.z, v.w);
        }
        float4* zo = (float4*)g_zp + (size_t)i * 8;
#pragma unroll
        for (int jj = 0; jj < 8; jj++) {
            float4 o;
            o.x = tanhf(acc[jj * 4 + 0] + __ldg(b1p + jj * 4 + 0));
            o.y = tanhf(acc[jj * 4 + 1] + __ldg(b1p + jj * 4 + 1));
            o.z = tanhf(acc[jj * 4 + 2] + __ldg(b1p + jj * 4 + 2));
            o.w = tanhf(acc[jj * 4 + 3] + __ldg(b1p + jj * 4 + 3));
            zo[jj] = o;
        }
    }
    // negative branch
    {
        float acc[32];
#pragma unroll
        for (int j = 0; j < 32; j++) acc[j] = 0.f;
        const float4* a4 = (const float4*)g_ansum + (size_t)i * 16;
#pragma unroll 2
        for (int kk = 0; kk < 16; kk++) {
            float4 v = a4[kk];
            acc_chunk(acc, Wn, kk * 4, v.x * invn, v.y * invn, v.z * invn, v.w * invn);
        }
#pragma unroll 2
        for (int kk = 0; kk < 16; kk++) {
            float4 v = x4[kk];
            acc_chunk(acc, Wn, 64 + kk * 4, v.x, v.y, v.z, v.w);
        }
        float4* zo = (float4*)g_zn + (size_t)i * 8;
#pragma unroll
        for (int jj = 0; jj < 8; jj++) {
            float4 o;
            o.x = tanhf(acc[jj * 4 + 0] + __ldg(b1n + jj * 4 + 0));
            o.y = tanhf(acc[jj * 4 + 1] + __ldg(b1n + jj * 4 + 1));
            o.z = tanhf(acc[jj * 4 + 2] + __ldg(b1n + jj * 4 + 2));
            o.w = tanhf(acc[jj * 4 + 3] + __ldg(b1n + jj * 4 + 3));
            zo[jj] = o;
        }
    }
}

// ---------------- layer-2 edge scatter: both features in one edge pass ------
// which=0 (pos edges): zp -> g_szpp, zn -> g_sznp
// which=1 (neg edges): zn -> g_sznn, zp -> g_szpn
__global__ void edge_l2(const void* __restrict__ ei, int E, int which) {
    const float* __restrict__ za = which ? g_zn : g_zp;
    const float* __restrict__ zb = which ? g_zp : g_zn;
    float* __restrict__ sa = which ? g_sznn : g_szpp;
    float* __restrict__ sb = which ? g_szpn : g_sznp;
    const int is64 = g_is64;
    long long total = (long long)E * 16;
    long long stride = (long long)gridDim.x * blockDim.x;
    for (long long item = (long long)blockIdx.x * blockDim.x + threadIdx.x;
         item < total; item += stride) {
        int e = (int)(item >> 4);
        int c = (int)(item & 15);
        int s = load_idx(ei, e, is64);
        int d = load_idx(ei, (long long)E + e, is64);
        if (c < 8) {
            float4 v = __ldg((const float4*)za + (size_t)s * 8 + c);
            red_add_v4(sa + (size_t)d * 32 + c * 4, v);
        } else {
            int cc = c - 8;
            float4 v = __ldg((const float4*)zb + (size_t)s * 8 + cc);
            red_add_v4(sb + (size_t)d * 32 + cc * 4, v);
        }
    }
}

// ---------------- layer-2 node update -> output -----------------------------
__global__ void node_l2(const float* __restrict__ W2p, const float* __restrict__ b2p,
                        const float* __restrict__ W2n, const float* __restrict__ b2n,
                        float* __restrict__ out, int n) {
    __shared__ float Wp[96 * 32];
    __shared__ float Wn[96 * 32];
    for (int t = threadIdx.x; t < 96 * 32; t += blockDim.x) { Wp[t] = W2p[t]; Wn[t] = W2n[t]; }
    __syncthreads();
    int i = blockIdx.x * blockDim.x + threadIdx.x;
    if (i >= n) return;

    float invp = 1.f / fmaxf(g_cntp[i], 1.f);
    float invn = 1.f / fmaxf(g_cntn[i], 1.f);

    // positive: [szpp/cp, sznn/cn, zp] @ W2p
    {
        float acc[32];
#pragma unroll
        for (int j = 0; j < 32; j++) acc[j] = 0.f;
        const float4* s0 = (const float4*)g_szpp + (size_t)i * 8;
        const float4* s1 = (const float4*)g_sznn + (size_t)i * 8;
        const float4* s2 = (const float4*)g_zp   + (size_t)i * 8;
#pragma unroll 2
        for (int kk = 0; kk < 8; kk++) {
            float4 v = s0[kk];
            acc_chunk(acc, Wp, kk * 4, v.x * invp, v.y * invp, v.z * invp, v.w * invp);
        }
#pragma unroll 2
        for (int kk = 0; kk < 8; kk++) {
            float4 v = s1[kk];
            acc_chunk(acc, Wp, 32 + kk * 4, v.x * invn, v.y * invn, v.z * invn, v.w * invn);
        }
#pragma unroll 2
        for (int kk = 0; kk < 8; kk++) {
            float4 v = s2[kk];
            acc_chunk(acc, Wp, 64 + kk * 4, v.x, v.y, v.z, v.w);
        }
        float4* o4 = (float4*)(out + (size_t)i * 64);
#pragma unroll
        for (int jj = 0; jj < 8; jj++) {
            float4 o;
            o.x = tanhf(acc[jj * 4 + 0] + __ldg(b2p + jj * 4 + 0));
            o.y = tanhf(acc[jj * 4 + 1] + __ldg(b2p + jj * 4 + 1));
            o.z = tanhf(acc[jj * 4 + 2] + __ldg(b2p + jj * 4 + 2));
            o.w = tanhf(acc[jj * 4 + 3] + __ldg(b2p + jj * 4 + 3));
            o4[jj] = o;
        }
    }
    // negative: [sznp/cp, szpn/cn, zn] @ W2n
    {
        float acc[32];
#pragma unroll
        for (int j = 0; j < 32; j++) acc[j] = 0.f;
        const float4* s0 = (const float4*)g_sznp + (size_t)i * 8;
        const float4* s1 = (const float4*)g_szpn + (size_t)i * 8;
        const float4* s2 = (const float4*)g_zn   + (size_t)i * 8;
#pragma unroll 2
        for (int kk = 0; kk < 8; kk++) {
            float4 v = s0[kk];
            acc_chunk(acc, Wn, kk * 4, v.x * invp, v.y * invp, v.z * invp, v.w * invp);
        }
#pragma unroll 2
        for (int kk = 0; kk < 8; kk++) {
            float4 v = s1[kk];
            acc_chunk(acc, Wn, 32 + kk * 4, v.x * invn, v.y * invn, v.z * invn, v.w * invn);
        }
#pragma unroll 2
        for (int kk = 0; kk < 8; kk++) {
            float4 v = s2[kk];
            acc_chunk(acc, Wn, 64 + kk * 4, v.x, v.y, v.z, v.w);
        }
        float4* o4 = (float4*)(out + (size_t)i * 64 + 32);
#pragma unroll
        for (int jj = 0; jj < 8; jj++) {
            float4 o;
            o.x = tanhf(acc[jj * 4 + 0] + __ldg(b2n + jj * 4 + 0));
            o.y = tanhf(acc[jj * 4 + 1] + __ldg(b2n + jj * 4 + 1));
            o.z = tanhf(acc[jj * 4 + 2] + __ldg(b2n + jj * 4 + 2));
            o.w = tanhf(acc[jj * 4 + 3] + __ldg(b2n + jj * 4 + 3));
            o4[jj] = o;
        }
    }
}

// ---------------- launch -----------------------------------------------------
extern "C" void kernel_launch(void* const* d_in, const int* in_sizes, int n_in,
                              void* d_out, int out_size) {
    const float* x   = (const float*)d_in[0];
    const float* W1p = (const float*)d_in[1];
    const float* b1p = (const float*)d_in[2];
    const float* W1n = (const float*)d_in[3];
    const float* b1n = (const float*)d_in[4];
    const float* W2p = (const float*)d_in[5];
    const float* b2p = (const float*)d_in[6];
    const float* W2n = (const float*)d_in[7];
    const float* b2n = (const float*)d_in[8];
    const void* pe = d_in[9];
    const void* ne = d_in[10];

    int n = in_sizes[0] / 64;
    int E = in_sizes[9] / 2;
    float* out = (float*)d_out;

    detect_dtype<<<1, 1>>>((const unsigned int*)pe);
    zero_all<<<1184, 256>>>(n);

    edge_l1<<<4096, 256>>>(pe, x, E, 1);
    edge_l1<<<4096, 256>>>(ne, x, E, 0);

    node_l1<<<(n + 255) / 256, 256>>>(x, W1p, b1p, W1n, b1n, n);

    edge_l2<<<4096, 256>>>(pe, E, 0);
    edge_l2<<<4096, 256>>>(ne, E, 1);

    node_l2<<<(n + 255) / 256, 256>>>(W2p, b2p, W2n, b2n, out, n);
}